// round 1
// baseline (speedup 1.0000x reference)
#include <cuda_runtime.h>

#define HH 128
#define WW 128
#define HW 16384
#define NB 2

// ---------------- scratch (no allocations allowed) ----------------
__device__ float g_xup[NB * 256 * HW];     // upsampled x_high
__device__ float g_xmerge[NB * 256 * HW];  // concat(f_low, f_high)
__device__ float g_offset[NB * 18 * HW];
__device__ float g_mask[NB * 9 * HW];

// ---------------- 1) bilinear 2x upsample (half-pixel, clamp == jax renorm) ---
__global__ void upsample_kernel(const float* __restrict__ xh) {
    int idx = blockIdx.x * 256 + threadIdx.x;   // total 2*256*128*128 = 8388608
    int x = idx & 127;
    int y = (idx >> 7) & 127;
    int bc = idx >> 14;                          // b*256 + c
    float sy = (y + 0.5f) * 0.5f - 0.5f;
    float sx = (x + 0.5f) * 0.5f - 0.5f;
    float y0f = floorf(sy), x0f = floorf(sx);
    float fy = sy - y0f, fx = sx - x0f;
    int y0 = (int)y0f, x0 = (int)x0f;
    int y0c = max(y0, 0), y1c = min(y0 + 1, 63);
    int x0c = max(x0, 0), x1c = min(x0 + 1, 63);
    const float* p = xh + (size_t)bc * 4096;
    float v00 = p[y0c * 64 + x0c], v01 = p[y0c * 64 + x1c];
    float v10 = p[y1c * 64 + x0c], v11 = p[y1c * 64 + x1c];
    g_xup[idx] = (1.f - fy) * ((1.f - fx) * v00 + fx * v01)
               + fy * ((1.f - fx) * v10 + fx * v11);
}

// ---------------- 2) conv3x3 (SAME) + BN + ReLU -> g_xmerge[chan_base..] -----
// block: 16x16 threads, tile 32x32 pixels (4 quadrant pixels/thread) x 16 co
template <int CIN>
__global__ void __launch_bounds__(256, 2) conv3x3_bn_relu(
    const float* __restrict__ x, const float* __restrict__ w,
    const float* __restrict__ gg, const float* __restrict__ bbp,
    const float* __restrict__ mmp, const float* __restrict__ vvp,
    int chan_base)
{
    __shared__ float patch[34 * 34];
    __shared__ float ws[144];

    int bz = blockIdx.z;
    int b   = bz >> 3;
    int co0 = (bz & 7) << 4;
    int x0 = blockIdx.x << 5, y0 = blockIdx.y << 5;
    int tx = threadIdx.x, ty = threadIdx.y;
    int tid = ty * 16 + tx;

    float acc[64];
#pragma unroll
    for (int i = 0; i < 64; i++) acc[i] = 0.f;

    const float* xb = x + (size_t)b * CIN * HW;

    for (int ci = 0; ci < CIN; ci++) {
        __syncthreads();
        for (int i = tid; i < 34 * 34; i += 256) {
            int py = i / 34, px = i % 34;
            int gy = y0 + py - 1, gx = x0 + px - 1;
            float v = 0.f;
            if (gy >= 0 && gy < HH && gx >= 0 && gx < WW)
                v = xb[(size_t)ci * HW + gy * WW + gx];
            patch[i] = v;
        }
        if (tid < 144)
            ws[tid] = w[((size_t)(co0 + tid / 9) * CIN + ci) * 9 + tid % 9];
        __syncthreads();

        float pv[4][9];
#pragma unroll
        for (int q = 0; q < 4; q++) {
            int py = ty + ((q >> 1) << 4);
            int px = tx + ((q & 1) << 4);
#pragma unroll
            for (int k = 0; k < 9; k++)
                pv[q][k] = patch[(py + k / 3) * 34 + px + (k % 3)];
        }
#pragma unroll
        for (int co = 0; co < 16; co++) {
#pragma unroll
            for (int k = 0; k < 9; k++) {
                float wv = ws[co * 9 + k];
#pragma unroll
                for (int q = 0; q < 4; q++)
                    acc[co * 4 + q] = fmaf(wv, pv[q][k], acc[co * 4 + q]);
            }
        }
    }

    // BN + ReLU epilogue
#pragma unroll
    for (int co = 0; co < 16; co++) {
        int c = co0 + co;
        float s = gg[c] * rsqrtf(vvp[c] + 1e-5f);
        float t = bbp[c] - mmp[c] * s;
#pragma unroll
        for (int q = 0; q < 4; q++) {
            int py = y0 + ty + ((q >> 1) << 4);
            int px = x0 + tx + ((q & 1) << 4);
            float r = fmaxf(acc[co * 4 + q] * s + t, 0.f);
            g_xmerge[((size_t)b * 256 + chan_base + c) * HW + py * WW + px] = r;
        }
    }
}

// ---------------- 3) 1x1 convs: offset (18) + mask (9, sigmoid) --------------
// 64 blocks x 256 threads, 2 pixels/thread; all 27x256 weights in smem
__global__ void __launch_bounds__(256) offmask_kernel(
    const float* __restrict__ w_off, const float* __restrict__ b_off,
    const float* __restrict__ w_mask, const float* __restrict__ b_mask)
{
    __shared__ float wsm[27 * 256];
    int tid = threadIdx.x;
    for (int i = tid; i < 27 * 256; i += 256)
        wsm[i] = (i < 18 * 256) ? w_off[i] : w_mask[i - 18 * 256];
    __syncthreads();

    int start = blockIdx.x * 512;           // 32 blocks per batch: no straddle
    int b = start >> 14;
    int pix = (start & 16383) + 2 * tid;
    const float* xm = g_xmerge + (size_t)b * 256 * HW + pix;

    float acc0[27], acc1[27];
#pragma unroll
    for (int o = 0; o < 27; o++) { acc0[o] = 0.f; acc1[o] = 0.f; }

    for (int c = 0; c < 256; c++) {
        float2 xv = *(const float2*)(xm + (size_t)c * HW);
#pragma unroll
        for (int o = 0; o < 27; o++) {
            float wv = wsm[o * 256 + c];
            acc0[o] = fmaf(wv, xv.x, acc0[o]);
            acc1[o] = fmaf(wv, xv.y, acc1[o]);
        }
    }
#pragma unroll
    for (int o = 0; o < 18; o++) {
        float bias = b_off[o];
        float* dst = g_offset + ((size_t)b * 18 + o) * HW + pix;
        dst[0] = acc0[o] + bias;
        dst[1] = acc1[o] + bias;
    }
#pragma unroll
    for (int o = 0; o < 9; o++) {
        float bias = b_mask[o];
        float a0 = acc0[18 + o] + bias, a1 = acc1[18 + o] + bias;
        float* dst = g_mask + ((size_t)b * 9 + o) * HW + pix;
        dst[0] = 1.f / (1.f + expf(-a0));
        dst[1] = 1.f / (1.f + expf(-a1));
    }
}

// ---------------- 4) deformable conv 3x3 + ReLU ------------------------------
// block: 8x8 pixel tile x 64 co, 256 threads; thread = 4 co x 4 px.
// Per-(pixel,tap) meta (4 clipped corner indices + mask-folded bilinear
// weights) computed once; cin looped in chunks of 4 through smem.
__global__ void __launch_bounds__(256) deform_kernel(
    const float* __restrict__ wconv, float* __restrict__ out)
{
    __shared__ int   mI0[576], mI1[576], mI2[576], mI3[576];
    __shared__ float mW0[576], mW1[576], mW2[576], mW3[576];
    __shared__ __align__(16) float vals[4 * 9 * 64];   // [cc][k][p]
    __shared__ float ws[64 * 36];                      // [co][ck]

    int bz = blockIdx.z;
    int b   = bz >> 1;
    int co0 = (bz & 1) << 6;
    int gx0 = blockIdx.x << 3, gy0 = blockIdx.y << 3;
    int tid = threadIdx.x;

    // setup: each thread writes entries e = tid, tid+256, tid+512 and will
    // read back exactly the same set (no cross-thread dep before first sync)
    for (int e = tid; e < 576; e += 256) {
        int p = e & 63, k = e >> 6;
        int gy = gy0 + (p >> 3), gx = gx0 + (p & 7);
        int pix = gy * WW + gx;
        float dy = g_offset[((size_t)b * 18 + 2 * k) * HW + pix];
        float dx = g_offset[((size_t)b * 18 + 2 * k + 1) * HW + pix];
        float mk = g_mask[((size_t)b * 9 + k) * HW + pix];
        float ys = (float)gy + (float)(k / 3 - 1) + dy;
        float xs = (float)gx + (float)(k % 3 - 1) + dx;
        float y0f = floorf(ys), x0f = floorf(xs);
        int y0 = (int)y0f, x0 = (int)x0f;
        float wy = ys - y0f, wx = xs - x0f;
        bool vy0 = (y0 >= 0) && (y0 < HH);
        bool vy1 = (y0 + 1 >= 0) && (y0 + 1 < HH);
        bool vx0 = (x0 >= 0) && (x0 < WW);
        bool vx1 = (x0 + 1 >= 0) && (x0 + 1 < WW);
        int y0c = min(max(y0, 0), HH - 1), y1c = min(max(y0 + 1, 0), HH - 1);
        int x0c = min(max(x0, 0), WW - 1), x1c = min(max(x0 + 1, 0), WW - 1);
        mI0[e] = y0c * WW + x0c;  mW0[e] = (vy0 && vx0) ? (1.f - wy) * (1.f - wx) * mk : 0.f;
        mI1[e] = y0c * WW + x1c;  mW1[e] = (vy0 && vx1) ? (1.f - wy) * wx * mk : 0.f;
        mI2[e] = y1c * WW + x0c;  mW2[e] = (vy1 && vx0) ? wy * (1.f - wx) * mk : 0.f;
        mI3[e] = y1c * WW + x1c;  mW3[e] = (vy1 && vx1) ? wy * wx * mk : 0.f;
    }

    float acc[16];
#pragma unroll
    for (int i = 0; i < 16; i++) acc[i] = 0.f;

    const float* xb = g_xmerge + (size_t)b * 256 * HW;
    int pgi = tid & 15;      // pixel group: pixels pgi*4 .. pgi*4+3
    int cgi = tid >> 4;      // co group:    cos    cgi*4 .. cgi*4+3

    for (int c0 = 0; c0 < 256; c0 += 4) {
        __syncthreads();     // previous GEMM done reading vals/ws
        // gather
        for (int e = tid; e < 576; e += 256) {
            int i0 = mI0[e], i1 = mI1[e], i2 = mI2[e], i3 = mI3[e];
            float w0 = mW0[e], w1 = mW1[e], w2 = mW2[e], w3 = mW3[e];
            int p = e & 63, k = e >> 6;
#pragma unroll
            for (int cc = 0; cc < 4; cc++) {
                const float* xc = xb + (size_t)(c0 + cc) * HW;
                vals[(cc * 9 + k) * 64 + p] =
                    w0 * xc[i0] + w1 * xc[i1] + w2 * xc[i2] + w3 * xc[i3];
            }
        }
        // weights for this chunk: ws[co][ck], ck = cc*9+k
        for (int i = tid; i < 64 * 36; i += 256) {
            int co = i / 36, ck = i % 36;
            ws[i] = wconv[(size_t)(co0 + co) * 2304 + c0 * 9 + ck];
        }
        __syncthreads();
        // GEMM: acc[j][r] += ws[cgi*4+j][ck] * vals[ck][pgi*4+r]
#pragma unroll
        for (int ck = 0; ck < 36; ck++) {
            float4 v4 = *(const float4*)&vals[ck * 64 + pgi * 4];
#pragma unroll
            for (int j = 0; j < 4; j++) {
                float wv = ws[(cgi * 4 + j) * 36 + ck];
                acc[j * 4 + 0] = fmaf(wv, v4.x, acc[j * 4 + 0]);
                acc[j * 4 + 1] = fmaf(wv, v4.y, acc[j * 4 + 1]);
                acc[j * 4 + 2] = fmaf(wv, v4.z, acc[j * 4 + 2]);
                acc[j * 4 + 3] = fmaf(wv, v4.w, acc[j * 4 + 3]);
            }
        }
    }

    // epilogue: ReLU + store
#pragma unroll
    for (int j = 0; j < 4; j++) {
        int co = co0 + cgi * 4 + j;
#pragma unroll
        for (int r = 0; r < 4; r++) {
            int p = pgi * 4 + r;
            int gy = gy0 + (p >> 3), gx = gx0 + (p & 7);
            out[((size_t)b * 128 + co) * HW + gy * WW + gx] =
                fmaxf(acc[j * 4 + r], 0.f);
        }
    }
}

// ---------------- launch -----------------------------------------------------
extern "C" void kernel_launch(void* const* d_in, const int* in_sizes, int n_in,
                              void* d_out, int out_size) {
    const float* x_low  = (const float*)d_in[0];
    const float* x_high = (const float*)d_in[1];
    const float* w_low  = (const float*)d_in[2];
    const float* g_low  = (const float*)d_in[3];
    const float* b_low  = (const float*)d_in[4];
    const float* m_low  = (const float*)d_in[5];
    const float* v_low  = (const float*)d_in[6];
    const float* w_high = (const float*)d_in[7];
    const float* g_high = (const float*)d_in[8];
    const float* b_high = (const float*)d_in[9];
    const float* m_high = (const float*)d_in[10];
    const float* v_high = (const float*)d_in[11];
    const float* w_off  = (const float*)d_in[12];
    const float* b_off  = (const float*)d_in[13];
    const float* w_mask = (const float*)d_in[14];
    const float* b_mask = (const float*)d_in[15];
    const float* w_conv = (const float*)d_in[16];
    float* out = (float*)d_out;

    void* xup_ptr = nullptr;
    cudaGetSymbolAddress(&xup_ptr, g_xup);

    upsample_kernel<<<(NB * 256 * HW) / 256, 256>>>(x_high);

    dim3 cb(16, 16);
    conv3x3_bn_relu<128><<<dim3(4, 4, 16), cb>>>(
        x_low, w_low, g_low, b_low, m_low, v_low, 0);
    conv3x3_bn_relu<256><<<dim3(4, 4, 16), cb>>>(
        (const float*)xup_ptr, w_high, g_high, b_high, m_high, v_high, 128);

    offmask_kernel<<<64, 256>>>(w_off, b_off, w_mask, b_mask);

    deform_kernel<<<dim3(16, 16, NB * 2), 256>>>(w_conv, out);
}